// round 17
// baseline (speedup 1.0000x reference)
#include <cuda_runtime.h>
#include <cstdint>

#define EN 2048
#define IN_ 256
#define TN 256
#define BN 32
#define EWORDS 64
#define IWORDS 8
#define NT 576   // 512 exc threads (warps 0-15) + 64 dedicated inh threads (warps 16-17)
#define CLN 4    // CTAs per cluster; batch = cluster

// packed w_rec, sim-load-friendly layout: g_wrecC[((j>>9)*16+g)*512 + (j&511)]
__device__ __align__(16) uint4 g_wrecC[EN * 16];   // 512KB
__device__ float g_rowsum[EN];    // exact popcount of row j
__device__ float g_cs_wie[EN];    // sum_i w_ie[i][j] (ascending i)
__device__ float g_cs_wei[IN_];   // sum_e w_ei[e][i] (ascending e)
__device__ int      g_rsmin;
__device__ uint32_t g_cwie_max_u, g_xmax_u;

// ---------------- prep 1: pack w_rec + reset markers ----------------
__global__ void prep1(const float* __restrict__ wrec) {
    if (blockIdx.x == 0 && threadIdx.x == 0) {
        g_rsmin = 0x7fffffff; g_cwie_max_u = 0u; g_xmax_u = 0u;
    }
    int idx = blockIdx.x * 256 + threadIdx.x;   // 32768 tasks: (j, g)
    int j = idx >> 4, g = idx & 15;
    const uint4* p = reinterpret_cast<const uint4*>(wrec + (size_t)j * EN + g * 128);
    uint32_t wd[4];
#pragma unroll
    for (int w4 = 0; w4 < 4; w4++) {
        uint32_t m = 0;
#pragma unroll
        for (int k = 0; k < 8; k++) {
            uint4 f = p[w4 * 8 + k];   // entries exactly 0.0f or 1.0f
            m |= (f.x ? 1u : 0u) << (k * 4 + 0);
            m |= (f.y ? 1u : 0u) << (k * 4 + 1);
            m |= (f.z ? 1u : 0u) << (k * 4 + 2);
            m |= (f.w ? 1u : 0u) << (k * 4 + 3);
        }
        wd[w4] = m;
    }
    g_wrecC[((j >> 9) * 16 + g) * 512 + (j & 511)] = make_uint4(wd[0], wd[1], wd[2], wd[3]);
}

// ---------------- prep 2: sums + invariant bounds + max|x| ----------------
__global__ void prep2(const float* __restrict__ x,
                      const float* __restrict__ wie,
                      const float* __restrict__ wei) {
    const int bid = blockIdx.x, tid = threadIdx.x, lane = tid & 31;
    if (bid < 8) {
        int j = bid * 256 + tid;
        int r = j >> 9, tt = j & 511;
        int cnt = 0;
#pragma unroll
        for (int g = 0; g < 16; g++) {
            uint4 q = g_wrecC[(r * 16 + g) * 512 + tt];
            cnt += __popc(q.x) + __popc(q.y) + __popc(q.z) + __popc(q.w);
        }
        g_rowsum[j] = (float)cnt;
        atomicMin(&g_rsmin, cnt);
        float s = 0.f;
#pragma unroll 4
        for (int i = 0; i < IN_; i++) s = __fadd_rn(s, wie[(size_t)i * EN + j]);
        g_cs_wie[j] = s;
        atomicMax(&g_cwie_max_u, __float_as_uint(s));  // s >= 0: bits monotone
    } else if (bid == 8) {
        if (tid < IN_) {
            float q = 0.f;
#pragma unroll 4
            for (int e = 0; e < EN; e++) q = __fadd_rn(q, wei[(size_t)e * IN_ + tid]);
            g_cs_wei[tid] = q;
        }
    } else {
        const float4* x4 = reinterpret_cast<const float4*>(x);
        const int n4 = (TN * BN * EN) / 4;
        int i = (bid - 9) * 256 + tid;
        const int stride = 256 * 256;
        float m = 0.f;
        for (; i < n4; i += stride) {
            float4 f = x4[i];
            m = fmaxf(m, fmaxf(fmaxf(fabsf(f.x), fabsf(f.y)), fmaxf(fabsf(f.z), fabsf(f.w))));
        }
#pragma unroll
        for (int off = 16; off > 0; off >>= 1)
            m = fmaxf(m, __shfl_xor_sync(0xffffffffu, m, off));
        if (lane == 0) atomicMax(&g_xmax_u, __float_as_uint(m));
    }
}

// ---------------- cluster helpers ----------------
__device__ __forceinline__ uint32_t smem_u32(const void* p) {
    uint32_t a;
    asm("{ .reg .u64 t; cvta.to.shared.u64 t, %1; cvt.u32.u64 %0, t; }" : "=r"(a) : "l"(p));
    return a;
}
__device__ __forceinline__ void stc_u32(uint32_t la, uint32_t rk, uint32_t v) {
    uint32_t ra;
    asm volatile("mapa.shared::cluster.u32 %0, %1, %2;" : "=r"(ra) : "r"(la), "r"(rk));
    asm volatile("st.shared::cluster.u32 [%0], %1;" :: "r"(ra), "r"(v) : "memory");
}
__device__ __forceinline__ void stc_u16(uint32_t la, uint32_t rk, uint16_t v) {
    uint32_t ra;
    asm volatile("mapa.shared::cluster.u32 %0, %1, %2;" : "=r"(ra) : "r"(la), "r"(rk));
    asm volatile("st.shared::cluster.u16 [%0], %1;" :: "r"(ra), "h"(v) : "memory");
}

// ---------------- main simulator: 4-CTA cluster per batch, dedicated inh warps ----------------
// flag bits in s_fc low byte: b0=ea, b1=ey, b2=ia, b3=iy, b4=sa ; high byte = exc spike count
__global__ void __cluster_dims__(CLN, 1, 1) __launch_bounds__(NT, 1)
sim_kernel(const float* __restrict__ x,
           const float* __restrict__ wei,
           const float* __restrict__ wie,
           float* __restrict__ out)
{
    extern __shared__ __align__(16) uint4 s_wrec[];   // [16][512] = 128KB
    __shared__ __align__(16) uint32_t s_ez[2][EWORDS];
    __shared__ __align__(16) uint32_t s_iz[2][IWORDS];
    __shared__ __align__(16) uint16_t s_fc[2][80];    // 64 exc + 8 inh + 8 pad slots
    __shared__ uint16_t s_elist[2][1024];
    __shared__ uint16_t s_ilist[2][IN_];

    const int t = threadIdx.x;
    const int warp = t >> 5, lane = t & 31;
    const int b = blockIdx.x >> 2;
    uint32_t rank;
    asm("mov.u32 %0, %%cluster_ctarank;" : "=r"(rank));
    const bool is_exc = (t < 512);
    const int j  = (int)rank * 512 + t;            // exc neuron (valid if is_exc)
    const int li = t - 512;                        // local inh idx 0..63
    const int i0 = (int)rank * 64 + li;            // inh neuron (valid if !is_exc)

    // load this CTA's w_rec quarter into SMEM
    if (is_exc) {
#pragma unroll
        for (int g = 0; g < 16; g++)
            s_wrec[g * 512 + t] = g_wrecC[((int)rank * 16 + g) * 512 + t];
    }

    float v = 0.f, cu = 0.f, iv = 0.f, ii = 0.f;
    float rs = 0.f, cw = 0.f, cwei = 0.f;
    if (is_exc) { rs = g_rowsum[j]; cw = g_cs_wie[j]; }
    else        { cwei = g_cs_wei[i0]; }

    // absorbing-saturation invariant (exc-only, proven sufficient; see R8)
    const int g_ok =
        __fadd_rn((float)g_rsmin,
                  -__fadd_rn(__uint_as_float(g_cwie_max_u), __uint_as_float(g_xmax_u))) >= 13.0f;

    if (t < EWORDS) { s_ez[0][t] = 0u; s_ez[1][t] = 0u; }
    if (t < IWORDS) { s_iz[0][t] = 0u; s_iz[1][t] = 0u; }
    if (t < 8) { s_fc[0][72 + t] = 0x0015; s_fc[1][72 + t] = 0x0015; }  // neutral pads
    __syncthreads();

    int pe_all = 0, pe_any = 0, pi_all = 0, pi_any = 0;
    int ts = TN;

    // depth-2 x pipeline (exc threads only)
    float xc = 0.f, xn = 0.f;
    if (is_exc) {
        xc = x[(size_t)b * EN + j];
        xn = x[((size_t)1 * BN + b) * EN + j];
    }

    for (int st = 0; st < TN; st++) {
        const int wp = st & 1, rp = wp ^ 1;

        uint32_t eb = 0, sbal = 0, ibal = 0;
        float ii_dec = 0.f;

        if (is_exc) {
            // ---- [a] recurrent term: SMEM popcount (integer-exact) ----
            float rec;
            if (pe_all)       rec = rs;
            else if (!pe_any) rec = 0.f;
            else {
                int a = 0;
#pragma unroll
                for (int g = 0; g < 16; g++) {
                    uint4 q = s_wrec[g * 512 + t];
                    uint4 m = *reinterpret_cast<const uint4*>(&s_ez[rp][4 * g]);
                    a += __popc(m.x & q.x) + __popc(m.y & q.y)
                       + __popc(m.z & q.z) + __popc(m.w & q.w);
                }
                rec = (float)a;
            }

            // ---- [a] inhibitory feedback via iz list; complement caps chain at 128 ----
            float inh;
            if (pi_all)       inh = cw;
            else if (!pi_any) inh = 0.f;
            else {
                uint4 ma = *reinterpret_cast<const uint4*>(&s_iz[rp][0]);
                uint4 mb = *reinterpret_cast<const uint4*>(&s_iz[rp][4]);
                int icnt = __popc(ma.x) + __popc(ma.y) + __popc(ma.z) + __popc(ma.w)
                         + __popc(mb.x) + __popc(mb.y) + __popc(mb.z) + __popc(mb.w);
                int n = (icnt <= IN_ / 2) ? icnt : (IN_ - icnt);
                float s = 0.f;
#pragma unroll 4
                for (int k = 0; k < n; k++) {
                    int i = s_ilist[rp][k];
                    s = __fadd_rn(s, wie[(size_t)i * EN + j]);
                }
                inh = (icnt <= IN_ / 2) ? s : __fsub_rn(cw, s);
            }

            // ---- [b] excitatory update (JAX-exact rounding order) ----
            float id = __fadd_rn(cu, __fmul_rn(-0.2f, cu));
            float vd = __fadd_rn(v, __fmul_rn(0.1f, __fadd_rn(__fsub_rn(0.f, v), cu)));
            int z = __fsub_rn(vd, 1.0f) > 0.f;
            v = z ? 0.f : vd;
            cu = __fadd_rn(__fadd_rn(id, __fsub_rn(xc, inh)), rec);
            out[((size_t)st * BN + b) * EN + j] = z ? 1.f : 0.f;

            xc = xn;
            if (st + 2 < TN) xn = x[((size_t)(st + 2) * BN + b) * EN + j];

            int stable = g_ok && z && (cu >= 64.f);
            eb   = __ballot_sync(0xffffffffu, z);
            sbal = __ballot_sync(0xffffffffu, stable);
            if (lane == 0) {
                uint32_t ea = (eb == 0xffffffffu) ? 1u : 0u;
                uint32_t ey = (eb != 0u) ? 1u : 0u;
                uint32_t sa = (sbal == 0xffffffffu) ? 1u : 0u;
                // exc entry: ia=1 (neutral), iy=0
                uint16_t fc = (uint16_t)((ea | (ey << 1) | (1u << 2) | (sa << 4))
                                         | ((uint32_t)__popc(eb) << 8));
                uint32_t la_ez = smem_u32(&s_ez[wp][rank * 16 + warp]);
                uint32_t la_fc = smem_u32(&s_fc[wp][rank * 16 + warp]);
#pragma unroll
                for (uint32_t pr = 0; pr < CLN; pr++) {
                    stc_u32(la_ez, pr, eb);
                    stc_u16(la_fc, pr, fc);
                }
            }
        } else {
            // ---- inh decay + spike from OLD inh state ----
            ii_dec = __fadd_rn(ii, __fmul_rn(-0.2f, ii));
            float vi_dec = __fadd_rn(iv, __fmul_rn(0.1f, __fadd_rn(__fsub_rn(0.f, iv), ii)));
            int zi = __fsub_rn(vi_dec, 1.0f) > 0.f;
            iv = zi ? 0.f : vi_dec;

            ibal = __ballot_sync(0xffffffffu, zi);
            if (lane == 0) {
                uint32_t ia = (ibal == 0xffffffffu) ? 1u : 0u;
                uint32_t iy = (ibal != 0u) ? 1u : 0u;
                // inh entry: ea=1, ey=0, sa=1 (neutral), count=0
                uint16_t fc = (uint16_t)(1u | (ia << 2) | (iy << 3) | (1u << 4));
                int iw = warp - 16;  // 0 or 1
                uint32_t la_iz = smem_u32(&s_iz[wp][rank * 2 + iw]);
                uint32_t la_fc = smem_u32(&s_fc[wp][64 + rank * 2 + iw]);
#pragma unroll
                for (uint32_t pr = 0; pr < CLN; pr++) {
                    stc_u32(la_iz, pr, ibal);
                    stc_u16(la_fc, pr, fc);
                }
            }
        }

        // one cluster barrier per step: publishes all remote stores, syncs block
        asm volatile("barrier.cluster.arrive.aligned;" ::: "memory");
        asm volatile("barrier.cluster.wait.aligned;" ::: "memory");

        // ---- fold flags & counts (80 uint16, pads neutral) ----
        uint32_t fand = 0xffffffffu, forr = 0u;
        unsigned int csum = 0u;
        const uint4* fc4 = reinterpret_cast<const uint4*>(&s_fc[wp][0]);
#pragma unroll
        for (int q8 = 0; q8 < 10; q8++) {
            uint4 vfc = fc4[q8];
            fand &= (vfc.x | 0xff00ff00u) & (vfc.y | 0xff00ff00u)
                  & (vfc.z | 0xff00ff00u) & (vfc.w | 0xff00ff00u);
            forr |= (vfc.x & 0x00ff00ffu) | (vfc.y & 0x00ff00ffu)
                  | (vfc.z & 0x00ff00ffu) | (vfc.w & 0x00ff00ffu);
            csum = __dp4a((vfc.x >> 8) & 0x00ff00ffu, 0x01010101u, csum);
            csum = __dp4a((vfc.y >> 8) & 0x00ff00ffu, 0x01010101u, csum);
            csum = __dp4a((vfc.z >> 8) & 0x00ff00ffu, 0x01010101u, csum);
            csum = __dp4a((vfc.w >> 8) & 0x00ff00ffu, 0x01010101u, csum);
        }
        fand &= fand >> 16;  forr |= forr >> 16;
        int ne_all = fand & 1;        int ne_any = (forr >> 1) & 1;
        int ni_all = (fand >> 2) & 1; int ni_any = (forr >> 3) & 1;
        int ecnt = (int)csum;

        if ((fand >> 4) & 1) { ts = st + 1; break; }   // absorbing saturation (uniform)

        if (warp == 16) {
            // build elist[wp] (spikers or complement, ascending e)
            if (ne_any && !ne_all) {
                uint32_t w0 = s_ez[wp][2 * lane], w1 = s_ez[wp][2 * lane + 1];
                if (ecnt > 1024) { w0 = ~w0; w1 = ~w1; }
                int cnt = __popc(w0) + __popc(w1);
                int off = cnt;
#pragma unroll
                for (int d = 1; d < 32; d <<= 1) {
                    int nn = __shfl_up_sync(0xffffffffu, off, d);
                    if (lane >= d) off += nn;
                }
                off -= cnt;
                int be = lane * 64;
                while (w0) { int r = __ffs(w0) - 1; w0 &= w0 - 1;
                             s_elist[wp][off++] = (uint16_t)(be + r); }
                be += 32;
                while (w1) { int r = __ffs(w1) - 1; w1 &= w1 - 1;
                             s_elist[wp][off++] = (uint16_t)(be + r); }
            }
            asm volatile("bar.sync 2, 64;" ::: "memory");   // elist ready for both inh warps
        } else if (warp == 17) {
            // build ilist[wp] (spikers, ascending i)
            if (ni_any && !ni_all) {
                uint32_t m0 = (lane < IWORDS) ? s_iz[wp][lane] : 0u;
                int cnt = __popc(m0), off = cnt;
#pragma unroll
                for (int d = 1; d < 32; d <<= 1) {
                    int nn = __shfl_up_sync(0xffffffffu, off, d);
                    if (lane >= d) off += nn;
                }
                off -= cnt;
                int bi = lane * 32;
                while (m0) { int r = __ffs(m0) - 1; m0 &= m0 - 1;
                             s_ilist[wp][off++] = (uint16_t)(bi + r); }
            }
            asm volatile("bar.sync 1, 544;" ::: "memory");  // release exc readers of ilist
            asm volatile("bar.sync 2, 64;"  ::: "memory");  // wait for elist
        } else {
            asm volatile("bar.sync 1, 544;" ::: "memory");  // wait for ilist (warp 17)
        }

        // ---- [d] inhibitory current update (inh warps only; overlaps exc's next [a]) ----
        if (!is_exc) {
            float xi;
            if (ne_all)       xi = cwei;
            else if (!ne_any) xi = 0.f;
            else {
                int n = (ecnt <= 1024) ? ecnt : (EN - ecnt);
                float s = 0.f;
#pragma unroll 4
                for (int k = 0; k < n; k++) {
                    int e = s_elist[wp][k];
                    s = __fadd_rn(s, wei[(size_t)e * IN_ + i0]);
                }
                xi = (ecnt <= 1024) ? s : __fsub_rn(cwei, s);
            }
            ii = __fadd_rn(ii_dec, xi);
        }
        pe_all = ne_all; pe_any = ne_any; pi_all = ni_all; pi_any = ni_any;
    }

    // ---- fused fill: rows [ts, TN), this CTA writes its 512-float quarter ----
    const float4 ones = make_float4(1.f, 1.f, 1.f, 1.f);
    for (int r = ts; r < TN; r++) {
        if (t < 128) {
            float4* o4 = reinterpret_cast<float4*>(out + ((size_t)r * BN + b) * EN)
                       + (int)rank * 128 + t;
            __stcs(o4, ones);
        }
    }
}

extern "C" void kernel_launch(void* const* d_in, const int* in_sizes, int n_in,
                              void* d_out, int out_size)
{
    const float* x     = (const float*)d_in[0];  // [T,B,E]
    // d_in[1] = w_in (identity) -- exact pass-through, unused
    const float* w_rec = (const float*)d_in[2];  // [E,E]
    const float* w_ei  = (const float*)d_in[3];  // [E,I]
    const float* w_ie  = (const float*)d_in[4];  // [I,E]
    float* out = (float*)d_out;

    const int dsmem = 16 * 512 * sizeof(uint4);  // 128KB wrec quarter
    cudaFuncSetAttribute(sim_kernel, cudaFuncAttributeMaxDynamicSharedMemorySize, dsmem);

    prep1<<<128, 256>>>(w_rec);
    prep2<<<9 + 256, 256>>>(x, w_ie, w_ei);
    sim_kernel<<<BN * CLN, NT, dsmem>>>(x, w_ei, w_ie, out);
}